// round 9
// baseline (speedup 1.0000x reference)
#include <cuda_runtime.h>
#include <cuda_bf16.h>
#include <math.h>
#include <stdint.h>

#define BB 4
#define CC 512
#define TT 1024
#define HH 8
#define KCC 64
#define BHT (BB*HH)

// mma gemm pitch (proj kernels)
#define GP 136

__device__ float g_Q[BB*HH*TT*KCC];
__device__ float g_K[BB*HH*TT*KCC];
__device__ float g_V[BB*HH*TT*KCC];
__device__ float g_O[BB*HH*TT*KCC];

// ---------------------------------------------------------------------------
// helpers
// ---------------------------------------------------------------------------
__device__ __forceinline__ float f2tf32(float f) {
    unsigned int r;
    asm("cvt.rna.tf32.f32 %0, %1;" : "=r"(r) : "f"(f));
    return __uint_as_float(r);
}

__device__ __forceinline__ void mma_tf32(float c[4], unsigned int a0, unsigned int a1,
                                         unsigned int a2, unsigned int a3,
                                         unsigned int b0, unsigned int b1) {
    asm volatile(
        "mma.sync.aligned.m16n8k8.row.col.f32.tf32.tf32.f32 "
        "{%0,%1,%2,%3}, {%4,%5,%6,%7}, {%8,%9}, {%0,%1,%2,%3};"
        : "+f"(c[0]), "+f"(c[1]), "+f"(c[2]), "+f"(c[3])
        : "r"(a0), "r"(a1), "r"(a2), "r"(a3), "r"(b0), "r"(b1));
}

__device__ __forceinline__ unsigned bf2pack(float x, float y) {
    __nv_bfloat162 t = __floats2bfloat162_rn(x, y);
    return *reinterpret_cast<unsigned*>(&t);
}
__device__ __forceinline__ void split2(float x, float y, unsigned &hi, unsigned &lo) {
    __nv_bfloat16 hx = __float2bfloat16(x), hy = __float2bfloat16(y);
    float rx = x - __bfloat162float(hx);
    float ry = y - __bfloat162float(hy);
    __nv_bfloat162 H; H.x = hx; H.y = hy;
    hi = *reinterpret_cast<unsigned*>(&H);
    lo = bf2pack(rx, ry);
}
__device__ __forceinline__ void mma_bf16(float c[4], unsigned a0, unsigned a1,
                                         unsigned a2, unsigned a3,
                                         unsigned b0, unsigned b1) {
    asm volatile(
        "mma.sync.aligned.m16n8k16.row.col.f32.bf16.bf16.f32 "
        "{%0,%1,%2,%3},{%4,%5,%6,%7},{%8,%9},{%0,%1,%2,%3};"
        : "+f"(c[0]), "+f"(c[1]), "+f"(c[2]), "+f"(c[3])
        : "r"(a0), "r"(a1), "r"(a2), "r"(a3), "r"(b0), "r"(b1));
}
__device__ __forceinline__ void ldmx4(unsigned &r0, unsigned &r1, unsigned &r2, unsigned &r3,
                                      unsigned addr) {
    asm volatile("ldmatrix.sync.aligned.m8n8.x4.shared.b16 {%0,%1,%2,%3},[%4];"
        : "=r"(r0), "=r"(r1), "=r"(r2), "=r"(r3) : "r"(addr));
}
__device__ __forceinline__ void ldmx4t(unsigned &r0, unsigned &r1, unsigned &r2, unsigned &r3,
                                       unsigned addr) {
    asm volatile("ldmatrix.sync.aligned.m8n8.x4.trans.shared.b16 {%0,%1,%2,%3},[%4];"
        : "=r"(r0), "=r"(r1), "=r"(r2), "=r"(r3) : "r"(addr));
}

// ---------------------------------------------------------------------------
// Fused QKV projection, tf32 tensor-core, double-buffered prefetch (R8).
// ---------------------------------------------------------------------------
__global__ __launch_bounds__(256, 2)
void proj3_kernel(const float* __restrict__ wq, const float* __restrict__ bq,
                  const float* __restrict__ wk, const float* __restrict__ bk,
                  const float* __restrict__ wv, const float* __restrict__ bv,
                  const float* __restrict__ x,
                  float* __restrict__ pQ, float* __restrict__ pK, float* __restrict__ pV)
{
    const int z   = blockIdx.z;
    const int b   = z & 3;
    const int sel = z >> 2;
    const float* w    = (sel == 0) ? wq : (sel == 1) ? wk : wv;
    const float* bias = (sel == 0) ? bq : (sel == 1) ? bk : bv;
    float*       dst  = (sel == 0) ? pQ : (sel == 1) ? pK : pV;

    const int o0 = blockIdx.y * 128;
    const int t0 = blockIdx.x * 128;
    __shared__ float As[2][16][GP];
    __shared__ float Xs[2][16][GP];
    const int tid  = threadIdx.x;
    const int warp = tid >> 5, lane = tid & 31;
    const int m0 = (warp >> 1) * 32;
    const int n0 = (warp & 1) * 64;
    const int lq = lane >> 2, lr = lane & 3;
    const float* xb = x + (size_t)b * CC * TT;

    const int wr0 = (tid * 4) >> 4,          wk0 = (tid * 4) & 15;
    const int wr1 = (tid * 4 + 1024) >> 4,   wk1 = (tid * 4 + 1024) & 15;
    const int xk0 = (tid * 4) >> 7,          xt0 = (tid * 4) & 127;
    const int xk1 = (tid * 4 + 1024) >> 7,   xt1 = (tid * 4 + 1024) & 127;

    float acc[2][8][4] = {};
    float4 wv4[2], xv4[2];

    wv4[0] = *(const float4*)(w + (size_t)(o0 + wr0) * CC + wk0);
    wv4[1] = *(const float4*)(w + (size_t)(o0 + wr1) * CC + wk1);
    xv4[0] = *(const float4*)(xb + (size_t)xk0 * TT + t0 + xt0);
    xv4[1] = *(const float4*)(xb + (size_t)xk1 * TT + t0 + xt1);
    {
        As[0][wk0 + 0][wr0] = f2tf32(wv4[0].x); As[0][wk0 + 1][wr0] = f2tf32(wv4[0].y);
        As[0][wk0 + 2][wr0] = f2tf32(wv4[0].z); As[0][wk0 + 3][wr0] = f2tf32(wv4[0].w);
        As[0][wk1 + 0][wr1] = f2tf32(wv4[1].x); As[0][wk1 + 1][wr1] = f2tf32(wv4[1].y);
        As[0][wk1 + 2][wr1] = f2tf32(wv4[1].z); As[0][wk1 + 3][wr1] = f2tf32(wv4[1].w);
        float4 a = xv4[0];
        a.x = f2tf32(a.x); a.y = f2tf32(a.y); a.z = f2tf32(a.z); a.w = f2tf32(a.w);
        *(float4*)(&Xs[0][xk0][xt0]) = a;
        a = xv4[1];
        a.x = f2tf32(a.x); a.y = f2tf32(a.y); a.z = f2tf32(a.z); a.w = f2tf32(a.w);
        *(float4*)(&Xs[0][xk1][xt1]) = a;
    }
    __syncthreads();

    for (int k0 = 0; k0 < CC; k0 += 16) {
        const int cur = (k0 >> 4) & 1;
        const bool more = (k0 + 16) < CC;
        if (more) {
            const int kn = k0 + 16;
            wv4[0] = *(const float4*)(w + (size_t)(o0 + wr0) * CC + kn + wk0);
            wv4[1] = *(const float4*)(w + (size_t)(o0 + wr1) * CC + kn + wk1);
            xv4[0] = *(const float4*)(xb + (size_t)(kn + xk0) * TT + t0 + xt0);
            xv4[1] = *(const float4*)(xb + (size_t)(kn + xk1) * TT + t0 + xt1);
        }
        #pragma unroll
        for (int ks = 0; ks < 16; ks += 8) {
            unsigned int a[2][4];
            #pragma unroll
            for (int mi = 0; mi < 2; mi++) {
                int m = m0 + mi * 16;
                a[mi][0] = __float_as_uint(As[cur][ks + lr][m + lq]);
                a[mi][1] = __float_as_uint(As[cur][ks + lr][m + 8 + lq]);
                a[mi][2] = __float_as_uint(As[cur][ks + 4 + lr][m + lq]);
                a[mi][3] = __float_as_uint(As[cur][ks + 4 + lr][m + 8 + lq]);
            }
            #pragma unroll
            for (int nj = 0; nj < 8; nj++) {
                int n = n0 + nj * 8;
                unsigned int b0 = __float_as_uint(Xs[cur][ks + lr][n + lq]);
                unsigned int b1 = __float_as_uint(Xs[cur][ks + 4 + lr][n + lq]);
                mma_tf32(acc[0][nj], a[0][0], a[0][1], a[0][2], a[0][3], b0, b1);
                mma_tf32(acc[1][nj], a[1][0], a[1][1], a[1][2], a[1][3], b0, b1);
            }
        }
        if (more) {
            const int nxt = cur ^ 1;
            As[nxt][wk0 + 0][wr0] = f2tf32(wv4[0].x); As[nxt][wk0 + 1][wr0] = f2tf32(wv4[0].y);
            As[nxt][wk0 + 2][wr0] = f2tf32(wv4[0].z); As[nxt][wk0 + 3][wr0] = f2tf32(wv4[0].w);
            As[nxt][wk1 + 0][wr1] = f2tf32(wv4[1].x); As[nxt][wk1 + 1][wr1] = f2tf32(wv4[1].y);
            As[nxt][wk1 + 2][wr1] = f2tf32(wv4[1].z); As[nxt][wk1 + 3][wr1] = f2tf32(wv4[1].w);
            float4 a = xv4[0];
            a.x = f2tf32(a.x); a.y = f2tf32(a.y); a.z = f2tf32(a.z); a.w = f2tf32(a.w);
            *(float4*)(&Xs[nxt][xk0][xt0]) = a;
            a = xv4[1];
            a.x = f2tf32(a.x); a.y = f2tf32(a.y); a.z = f2tf32(a.z); a.w = f2tf32(a.w);
            *(float4*)(&Xs[nxt][xk1][xt1]) = a;
        }
        __syncthreads();
    }

    #pragma unroll
    for (int mi = 0; mi < 2; mi++) {
        #pragma unroll
        for (int half = 0; half < 2; half++) {
            int o = o0 + m0 + mi * 16 + half * 8 + lq;
            float bvv = bias[o];
            int h = o >> 6, kc = o & 63;
            float* drow = dst + ((size_t)(b * HH + h) * TT) * KCC + kc;
            #pragma unroll
            for (int nj = 0; nj < 8; nj++) {
                int t = t0 + n0 + nj * 8 + 2 * lr;
                drow[(size_t)t * KCC]       = acc[mi][nj][half * 2 + 0] + bvv;
                drow[(size_t)(t + 1) * KCC] = acc[mi][nj][half * 2 + 1] + bvv;
            }
        }
    }
}

// ---------------------------------------------------------------------------
// MMA banded flash attention, pipelined K/V feed.
// grid (T/128, BH), 256 thr. smem 83456 B -> 2 CTA/SM.
// ---------------------------------------------------------------------------
#define ATTN_SMEM 83456

__global__ __launch_bounds__(256, 2)
void attn_mma_kernel(const float* __restrict__ Q, const float* __restrict__ K,
                     const float* __restrict__ V, const float* __restrict__ embk,
                     const float* __restrict__ embv, float* __restrict__ Out)
{
    extern __shared__ char smem[];
    uint4* Qpk          = (uint4*)(smem);
    __nv_bfloat16* Khi  = (__nv_bfloat16*)(smem + 32768);
    __nv_bfloat16* Klo  = (__nv_bfloat16*)(smem + 41984);
    __nv_bfloat16* Vhi  = (__nv_bfloat16*)(smem + 51200);
    __nv_bfloat16* Vlo  = (__nv_bfloat16*)(smem + 60416);
    float* pe           = (float*)(smem + 69632);
    float* qe           = (float*)(smem + 74240);
    float* ek           = (float*)(smem + 78848);
    float* ev           = (float*)(smem + 81152);
    float* Qs           = (float*)(smem + 32768);

    const int bh = blockIdx.y;
    const int t0 = blockIdx.x * 128;
    const int tid = threadIdx.x;
    const int w = tid >> 5, lane = tid & 31;
    const int lq = lane >> 2, lr = lane & 3;
    const int R0 = w * 16 + lq;

    for (int lin = tid; lin < 576; lin += 256) { ek[lin] = embk[lin]; ev[lin] = embv[lin]; }
    const float* Qg = Q + ((size_t)bh * TT + t0) * KCC;
    #pragma unroll
    for (int i = 0; i < 8; i++) {
        int lin = tid * 4 + i * 1024;
        int r = lin >> 6, c = lin & 63;
        *(float4*)(Qs + r * 68 + c) = *(const float4*)(Qg + r * 64 + c);
    }
    for (int lin = tid; lin < 1152; lin += 256) pe[lin] = 0.f;
    __syncthreads();

    for (int idx = tid; idx < 1152; idx += 256) {
        int r = idx / 9, d = idx - r * 9;
        float s = 0.f;
        #pragma unroll 8
        for (int c = 0; c < 64; c++) s += Qs[r * 68 + c] * ek[d * 64 + c];
        qe[idx] = s;
    }
    #pragma unroll
    for (int i = 0; i < 8; i++) {
        int ii = tid + i * 256;
        int r = ii >> 4, ks = (ii >> 2) & 3, l2 = ii & 3;
        int c0 = 16 * ks + 2 * l2;
        float x0 = Qs[r * 68 + c0],     x1 = Qs[r * 68 + c0 + 1];
        float x2 = Qs[r * 68 + c0 + 8], x3 = Qs[r * 68 + c0 + 9];
        unsigned h01, l01, h89, l89;
        split2(x0, x1, h01, l01);
        split2(x2, x3, h89, l89);
        Qpk[(r * 4 + ks) * 4 + l2] = make_uint4(h01, h89, l01, l89);
    }
    __syncthreads();

    const int mm = lane >> 3, r8 = lane & 7;
    const unsigned KhiB = (unsigned)__cvta_generic_to_shared(Khi);
    const unsigned KloB = (unsigned)__cvta_generic_to_shared(Klo);
    const unsigned VhiB = (unsigned)__cvta_generic_to_shared(Vhi);
    const unsigned VloB = (unsigned)__cvta_generic_to_shared(Vlo);
    const unsigned k_part = ((((mm >> 1) * 8 + r8) * 72) + (mm & 1) * 8) * 2;
    const unsigned v_part = ((((mm & 1) * 8 + r8) * 72) + (mm >> 1) * 8) * 2;

    // per-thread load coords (fixed): item i at row si, col ci
    int si[4], ci[4];
    #pragma unroll
    for (int i = 0; i < 4; i++) {
        int lin = tid * 4 + i * 1024;
        si[i] = lin >> 6; ci[i] = lin & 63;
    }

    float S[8][4];
    float O[8][4] = {};
    float mr[2] = {-1e30f, -1e30f};
    float lr2[2] = {0.f, 0.f};
    const int jlo = (t0 - 4) < 0 ? 0 : (t0 - 4) >> 6;
    const int jhi = ((t0 + 131) >> 6) > 15 ? 15 : (t0 + 131) >> 6;

    const float* Kbh = K + (size_t)bh * TT * KCC;
    const float* Vbh = V + (size_t)bh * TT * KCC;

    // prologue: prefetch K tile 0 into regs
    float4 kreg[4];
    #pragma unroll
    for (int i = 0; i < 4; i++) kreg[i] = *(const float4*)(Kbh + si[i] * 64 + ci[i]);

    for (int j = 0; j < 16; j++) {
        const int s0 = j * 64;

        // store K from prefetch regs
        #pragma unroll
        for (int i = 0; i < 4; i++) {
            unsigned h01, l01, h23, l23;
            split2(kreg[i].x, kreg[i].y, h01, l01);
            split2(kreg[i].z, kreg[i].w, h23, l23);
            *(uint2*)(Khi + si[i] * 72 + ci[i]) = make_uint2(h01, h23);
            *(uint2*)(Klo + si[i] * 72 + ci[i]) = make_uint2(l01, l23);
        }
        // issue V loads (consumed after softmax)
        float4 vreg[4];
        #pragma unroll
        for (int i = 0; i < 4; i++)
            vreg[i] = *(const float4*)(Vbh + (size_t)(s0 + si[i]) * 64 + ci[i]);
        __syncthreads();   // K visible

        // ---- S = Q K^T ----
        #pragma unroll
        for (int nt = 0; nt < 8; nt++)
            #pragma unroll
            for (int sl = 0; sl < 4; sl++) S[nt][sl] = 0.f;

        #pragma unroll
        for (int ks = 0; ks < 4; ks++) {
            uint4 qa = Qpk[((R0)     * 4 + ks) * 4 + lr];
            uint4 qb = Qpk[((R0 + 8) * 4 + ks) * 4 + lr];
            #pragma unroll
            for (int ntp = 0; ntp < 4; ntp++) {
                unsigned base = ntp * 2304 + ks * 32 + k_part;
                unsigned h0, h1, h2, h3, g0, g1, g2, g3;
                ldmx4(h0, h1, h2, h3, KhiB + base);
                ldmx4(g0, g1, g2, g3, KloB + base);
                mma_bf16(S[2*ntp],   qa.x, qb.x, qa.y, qb.y, h0, h1);
                mma_bf16(S[2*ntp+1], qa.x, qb.x, qa.y, qb.y, h2, h3);
                mma_bf16(S[2*ntp],   qa.z, qb.z, qa.w, qb.w, h0, h1);
                mma_bf16(S[2*ntp+1], qa.z, qb.z, qa.w, qb.w, h2, h3);
                mma_bf16(S[2*ntp],   qa.x, qb.x, qa.y, qb.y, g0, g1);
                mma_bf16(S[2*ntp+1], qa.x, qb.x, qa.y, qb.y, g2, g3);
            }
        }

        const bool band = (j >= jlo) && (j <= jhi);
        if (band) {
            #pragma unroll
            for (int nt = 0; nt < 8; nt++)
                #pragma unroll
                for (int sl = 0; sl < 4; sl++) {
                    int rl = R0 + ((sl >> 1) << 3);
                    int d = (s0 + nt * 8 + 2 * lr + (sl & 1)) - (t0 + rl) + 4;
                    if (d >= 0 && d <= 8) S[nt][sl] += qe[rl * 9 + d];
                }
        }
        #pragma unroll
        for (int nt = 0; nt < 8; nt++)
            #pragma unroll
            for (int sl = 0; sl < 4; sl++) S[nt][sl] *= 0.125f;

        // ---- online softmax ----
        float alpha[2];
        #pragma unroll
        for (int h = 0; h < 2; h++) {
            float mx = -1e30f;
            #pragma unroll
            for (int nt = 0; nt < 8; nt++)
                mx = fmaxf(mx, fmaxf(S[nt][2*h], S[nt][2*h+1]));
            mx = fmaxf(mx, __shfl_xor_sync(0xffffffffu, mx, 1));
            mx = fmaxf(mx, __shfl_xor_sync(0xffffffffu, mx, 2));
            float mn = fmaxf(mr[h], mx);
            alpha[h] = __expf(mr[h] - mn);
            float rs = 0.f;
            #pragma unroll
            for (int nt = 0; nt < 8; nt++) {
                float p0 = __expf(S[nt][2*h]   - mn);
                float p1 = __expf(S[nt][2*h+1] - mn);
                S[nt][2*h] = p0; S[nt][2*h+1] = p1;
                rs += p0 + p1;
            }
            rs += __shfl_xor_sync(0xffffffffu, rs, 1);
            rs += __shfl_xor_sync(0xffffffffu, rs, 2);
            lr2[h] = lr2[h] * alpha[h] + rs;
            mr[h] = mn;
            #pragma unroll
            for (int nt = 0; nt < 8; nt++) { O[nt][2*h] *= alpha[h]; O[nt][2*h+1] *= alpha[h]; }
        }

        // store V (loads have had S+softmax to land)
        #pragma unroll
        for (int i = 0; i < 4; i++) {
            unsigned h01, l01, h23, l23;
            split2(vreg[i].x, vreg[i].y, h01, l01);
            split2(vreg[i].z, vreg[i].w, h23, l23);
            *(uint2*)(Vhi + si[i] * 72 + ci[i]) = make_uint2(h01, h23);
            *(uint2*)(Vlo + si[i] * 72 + ci[i]) = make_uint2(l01, l23);
        }

        if (lr == 0) {
            #pragma unroll
            for (int h = 0; h < 2; h++)
                if (alpha[h] != 1.0f) {
                    #pragma unroll
                    for (int d = 0; d < 9; d++) pe[(R0 + 8*h) * 9 + d] *= alpha[h];
                }
        }
        __syncwarp();
        if (band) {
            #pragma unroll
            for (int nt = 0; nt < 8; nt++)
                #pragma unroll
                for (int sl = 0; sl < 4; sl++) {
                    int rl = R0 + ((sl >> 1) << 3);
                    int d = (s0 + nt * 8 + 2 * lr + (sl & 1)) - (t0 + rl) + 4;
                    if (d >= 0 && d <= 8) pe[rl * 9 + d] += S[nt][sl];
                }
        }
        __syncthreads();   // V visible; all warps past K reads

        // prefetch K for next tile (hidden behind PV section)
        if (j < 15) {
            #pragma unroll
            for (int i = 0; i < 4; i++)
                kreg[i] = *(const float4*)(Kbh + (size_t)(s0 + 64 + si[i]) * 64 + ci[i]);
        }

        // ---- O += P V ----
        #pragma unroll
        for (int kp = 0; kp < 4; kp++) {
            unsigned aH0, aH1, aH2, aH3, aL0, aL1, aL2, aL3;
            split2(S[2*kp][0],   S[2*kp][1],   aH0, aL0);
            split2(S[2*kp][2],   S[2*kp][3],   aH1, aL1);
            split2(S[2*kp+1][0], S[2*kp+1][1], aH2, aL2);
            split2(S[2*kp+1][2], S[2*kp+1][3], aH3, aL3);
            #pragma unroll
            for (int ntp = 0; ntp < 4; ntp++) {
                unsigned base = kp * 2304 + ntp * 32 + v_part;
                unsigned h0, h1, h2, h3, g0, g1, g2, g3;
                ldmx4t(h0, h1, h2, h3, VhiB + base);
                ldmx4t(g0, g1, g2, g3, VloB + base);
                mma_bf16(O[2*ntp],   aH0, aH1, aH2, aH3, h0, h1);
                mma_bf16(O[2*ntp+1], aH0, aH1, aH2, aH3, h2, h3);
                mma_bf16(O[2*ntp],   aL0, aL1, aL2, aL3, h0, h1);
                mma_bf16(O[2*ntp+1], aL0, aL1, aL2, aL3, h2, h3);
                mma_bf16(O[2*ntp],   aH0, aH1, aH2, aH3, g0, g1);
                mma_bf16(O[2*ntp+1], aH0, aH1, aH2, aH3, g2, g3);
            }
        }
        __syncthreads();   // all warps past V reads before next V store... (K store next iter is a different buffer, but V store mid-next-iter needs this)
    }

    float pev0[9], pev1[9];
    #pragma unroll
    for (int d = 0; d < 9; d++) { pev0[d] = pe[R0 * 9 + d]; pev1[d] = pe[(R0 + 8) * 9 + d]; }
    const float il0 = 1.f / lr2[0], il1 = 1.f / lr2[1];
    float* Og = Out + ((size_t)bh * TT + t0) * KCC;
    #pragma unroll
    for (int nt = 0; nt < 8; nt++) {
        int c = nt * 8 + 2 * lr;
        float e0 = 0.f, e1 = 0.f, f0 = 0.f, f1 = 0.f;
        #pragma unroll
        for (int d = 0; d < 9; d++) {
            float v0 = ev[d * 64 + c], v1 = ev[d * 64 + c + 1];
            e0 += pev0[d] * v0; e1 += pev0[d] * v1;
            f0 += pev1[d] * v0; f1 += pev1[d] * v1;
        }
        *(float2*)(Og + (size_t)R0 * 64 + c)       = make_float2((O[nt][0] + e0) * il0,
                                                                 (O[nt][1] + e1) * il0);
        *(float2*)(Og + (size_t)(R0 + 8) * 64 + c) = make_float2((O[nt][2] + f0) * il1,
                                                                 (O[nt][3] + f1) * il1);
    }
}

// ---------------------------------------------------------------------------
// Output projection, tf32 tensor-core, double-buffered prefetch (R8).
// ---------------------------------------------------------------------------
__global__ __launch_bounds__(256, 2)
void oproj_kernel(const float* __restrict__ w, const float* __restrict__ bias,
                  const float* __restrict__ A, float* __restrict__ out)
{
    const int b  = blockIdx.z;
    const int o0 = blockIdx.y * 128;
    const int t0 = blockIdx.x * 128;
    __shared__ float As[2][16][GP];
    __shared__ float Xs[2][16][GP];
    const int tid  = threadIdx.x;
    const int warp = tid >> 5, lane = tid & 31;
    const int m0 = (warp >> 1) * 32;
    const int n0 = (warp & 1) * 64;
    const int lq = lane >> 2, lr = lane & 3;

    const int wr0 = (tid * 4) >> 4,          wk0 = (tid * 4) & 15;
    const int wr1 = (tid * 4 + 1024) >> 4,   wk1 = (tid * 4 + 1024) & 15;
    const int xt0 = (tid * 4) >> 4,          xk0 = (tid * 4) & 15;
    const int xt1 = (tid * 4 + 1024) >> 4,   xk1 = (tid * 4 + 1024) & 15;

    float acc[2][8][4] = {};
    float4 wv4[2], xv4[2];

    wv4[0] = *(const float4*)(w + (size_t)(o0 + wr0) * CC + wk0);
    wv4[1] = *(const float4*)(w + (size_t)(o0 + wr1) * CC + wk1);
    xv4[0] = *(const float4*)(A + ((size_t)(b * HH + 0) * TT + t0 + xt0) * KCC + xk0);
    xv4[1] = *(const float4*)(A + ((size_t)(b * HH + 0) * TT + t0 + xt1) * KCC + xk1);
    {
        As[0][wk0 + 0][wr0] = f2tf32(wv4[0].x); As[0][wk0 + 1][wr0] = f2tf32(wv4[0].y);
        As[0][wk0 + 2][wr0] = f2tf32(wv4[0].z); As[0][wk0 + 3][wr0] = f2tf32(wv4[0].w);
        As[0][wk1 + 0][wr1] = f2tf32(wv4[1].x); As[0][wk1 + 1][wr1] = f2tf32(wv4[1].y);
        As[0][wk1 + 2][wr1] = f2tf32(wv4[1].z); As[0][wk1 + 3][wr1] = f2tf32(wv4[1].w);
        Xs[0][xk0 + 0][xt0] = f2tf32(xv4[0].x); Xs[0][xk0 + 1][xt0] = f2tf32(xv4[0].y);
        Xs[0][xk0 + 2][xt0] = f2tf32(xv4[0].z); Xs[0][xk0 + 3][xt0] = f2tf32(xv4[0].w);
        Xs[0][xk1 + 0][xt1] = f2tf32(xv4[1].x); Xs[0][xk1 + 1][xt1] = f2tf32(xv4[1].y);
        Xs[0][xk1 + 2][xt1] = f2tf32(xv4[1].z); Xs[0][xk1 + 3][xt1] = f2tf32(xv4[1].w);
    }
    __syncthreads();

    for (int k0 = 0; k0 < CC; k0 += 16) {
        const int cur = (k0 >> 4) & 1;
        const bool more = (k0 + 16) < CC;
        if (more) {
            const int kn = k0 + 16;
            const int h = kn >> 6, kc0 = kn & 63;
            wv4[0] = *(const float4*)(w + (size_t)(o0 + wr0) * CC + kn + wk0);
            wv4[1] = *(const float4*)(w + (size_t)(o0 + wr1) * CC + kn + wk1);
            xv4[0] = *(const float4*)(A + ((size_t)(b * HH + h) * TT + t0 + xt0) * KCC + kc0 + xk0);
            xv4[1] = *(const float4*)(A + ((size_t)(b * HH + h) * TT + t0 + xt1) * KCC + kc0 + xk1);
        }
        #pragma unroll
        for (int ks = 0; ks < 16; ks += 8) {
            unsigned int a[2][4];
            #pragma unroll
            for (int mi = 0; mi < 2; mi++) {
                int m = m0 + mi * 16;
                a[mi][0] = __float_as_uint(As[cur][ks + lr][m + lq]);
                a[mi][1] = __float_as_uint(As[cur][ks + lr][m + 8 + lq]);
                a[mi][2] = __float_as_uint(As[cur][ks + 4 + lr][m + lq]);
                a[mi][3] = __float_as_uint(As[cur][ks + 4 + lr][m + 8 + lq]);
            }
            #pragma unroll
            for (int nj = 0; nj < 8; nj++) {
                int n = n0 + nj * 8;
                unsigned int b0 = __float_as_uint(Xs[cur][ks + lr][n + lq]);
                unsigned int b1 = __float_as_uint(Xs[cur][ks + 4 + lr][n + lq]);
                mma_tf32(acc[0][nj], a[0][0], a[0][1], a[0][2], a[0][3], b0, b1);
                mma_tf32(acc[1][nj], a[1][0], a[1][1], a[1][2], a[1][3], b0, b1);
            }
        }
        if (more) {
            const int nxt = cur ^ 1;
            As[nxt][wk0 + 0][wr0] = f2tf32(wv4[0].x); As[nxt][wk0 + 1][wr0] = f2tf32(wv4[0].y);
            As[nxt][wk0 + 2][wr0] = f2tf32(wv4[0].z); As[nxt][wk0 + 3][wr0] = f2tf32(wv4[0].w);
            As[nxt][wk1 + 0][wr1] = f2tf32(wv4[1].x); As[nxt][wk1 + 1][wr1] = f2tf32(wv4[1].y);
            As[nxt][wk1 + 2][wr1] = f2tf32(wv4[1].z); As[nxt][wk1 + 3][wr1] = f2tf32(wv4[1].w);
            Xs[nxt][xk0 + 0][xt0] = f2tf32(xv4[0].x); Xs[nxt][xk0 + 1][xt0] = f2tf32(xv4[0].y);
            Xs[nxt][xk0 + 2][xt0] = f2tf32(xv4[0].z); Xs[nxt][xk0 + 3][xt0] = f2tf32(xv4[0].w);
            Xs[nxt][xk1 + 0][xt1] = f2tf32(xv4[1].x); Xs[nxt][xk1 + 1][xt1] = f2tf32(xv4[1].y);
            Xs[nxt][xk1 + 2][xt1] = f2tf32(xv4[1].z); Xs[nxt][xk1 + 3][xt1] = f2tf32(xv4[1].w);
        }
        __syncthreads();
    }

    #pragma unroll
    for (int mi = 0; mi < 2; mi++) {
        #pragma unroll
        for (int half = 0; half < 2; half++) {
            int o = o0 + m0 + mi * 16 + half * 8 + lq;
            float bvv = bias[o];
            float* orow = out + ((size_t)b * CC + o) * TT;
            #pragma unroll
            for (int nj = 0; nj < 8; nj++) {
                int t = t0 + n0 + nj * 8 + 2 * lr;
                *(float2*)(orow + t) = make_float2(acc[mi][nj][half * 2 + 0] + bvv,
                                                   acc[mi][nj][half * 2 + 1] + bvv);
            }
        }
    }
}

// ---------------------------------------------------------------------------
extern "C" void kernel_launch(void* const* d_in, const int* in_sizes, int n_in,
                              void* d_out, int out_size)
{
    const float* x   = (const float*)d_in[0];
    const float* wq  = (const float*)d_in[1];
    const float* bq  = (const float*)d_in[2];
    const float* wk  = (const float*)d_in[3];
    const float* bk  = (const float*)d_in[4];
    const float* wv  = (const float*)d_in[5];
    const float* bv  = (const float*)d_in[6];
    const float* wo  = (const float*)d_in[7];
    const float* bo  = (const float*)d_in[8];
    const float* ek  = (const float*)d_in[9];
    const float* ev  = (const float*)d_in[10];
    float* out = (float*)d_out;

    float *pQ, *pK, *pV, *pO;
    cudaGetSymbolAddress((void**)&pQ, g_Q);
    cudaGetSymbolAddress((void**)&pK, g_K);
    cudaGetSymbolAddress((void**)&pV, g_V);
    cudaGetSymbolAddress((void**)&pO, g_O);

    static int configured = 0;
    if (!configured) {
        cudaFuncSetAttribute((const void*)attn_mma_kernel,
                             cudaFuncAttributeMaxDynamicSharedMemorySize, ATTN_SMEM);
        configured = 1;
    }

    proj3_kernel<<<dim3(TT / 128, CC / 128, BB * 3), 256>>>(wq, bq, wk, bk, wv, bv, x, pQ, pK, pV);
    attn_mma_kernel<<<dim3(TT / 128, BHT), 256, ATTN_SMEM>>>(pQ, pK, pV, ek, ev, pO);
    oproj_kernel<<<dim3(TT / 128, CC / 128, BB), 256>>>(wo, bo, pO, out);
}

// round 10
// speedup vs baseline: 1.2900x; 1.2900x over previous
#include <cuda_runtime.h>
#include <cuda_fp16.h>
#include <math.h>
#include <stdint.h>

#define BB 4
#define CC 512
#define TT 1024
#define HH 8
#define KCC 64
#define BHT (BB*HH)

__device__ float g_Q[BB*HH*TT*KCC];
__device__ float g_K[BB*HH*TT*KCC];
__device__ float g_V[BB*HH*TT*KCC];
__device__ float g_O[BB*HH*TT*KCC];

// ---------------------------------------------------------------------------
// helpers
// ---------------------------------------------------------------------------
__device__ __forceinline__ unsigned h2pack(float x, float y) {
    __half2 t = __floats2half2_rn(x, y);
    return *reinterpret_cast<unsigned*>(&t);
}
__device__ __forceinline__ void split2(float x, float y, unsigned &hi, unsigned &lo) {
    __half hx = __float2half_rn(x), hy = __float2half_rn(y);
    float rx = x - __half2float(hx);
    float ry = y - __half2float(hy);
    __half2 H; H.x = hx; H.y = hy;
    hi = *reinterpret_cast<unsigned*>(&H);
    lo = h2pack(rx, ry);
}
__device__ __forceinline__ void mma_f16(float c[4], unsigned a0, unsigned a1,
                                        unsigned a2, unsigned a3,
                                        unsigned b0, unsigned b1) {
    asm volatile(
        "mma.sync.aligned.m16n8k16.row.col.f32.f16.f16.f32 "
        "{%0,%1,%2,%3},{%4,%5,%6,%7},{%8,%9},{%0,%1,%2,%3};"
        : "+f"(c[0]), "+f"(c[1]), "+f"(c[2]), "+f"(c[3])
        : "r"(a0), "r"(a1), "r"(a2), "r"(a3), "r"(b0), "r"(b1));
}
__device__ __forceinline__ void ldmx4(unsigned &r0, unsigned &r1, unsigned &r2, unsigned &r3,
                                      unsigned addr) {
    asm volatile("ldmatrix.sync.aligned.m8n8.x4.shared.b16 {%0,%1,%2,%3},[%4];"
        : "=r"(r0), "=r"(r1), "=r"(r2), "=r"(r3) : "r"(addr));
}
__device__ __forceinline__ void ldmx4t(unsigned &r0, unsigned &r1, unsigned &r2, unsigned &r3,
                                       unsigned addr) {
    asm volatile("ldmatrix.sync.aligned.m8n8.x4.trans.shared.b16 {%0,%1,%2,%3},[%4];"
        : "=r"(r0), "=r"(r1), "=r"(r2), "=r"(r3) : "r"(addr));
}

// ---------------------------------------------------------------------------
// Fused QKV projection, fp16 HMMA + ldmatrix, double-buffered, BK=16.
// As[o][k] pitch 24 halves; Xs[k][t] pitch 136 halves (B via ldmatrix.trans).
// grid (T/128, C/128, B*3), 256 thr, warp tile 32x64.
// ---------------------------------------------------------------------------
__global__ __launch_bounds__(256, 2)
void proj3_kernel(const float* __restrict__ wq, const float* __restrict__ bq,
                  const float* __restrict__ wk, const float* __restrict__ bk,
                  const float* __restrict__ wv, const float* __restrict__ bv,
                  const float* __restrict__ x,
                  float* __restrict__ pQ, float* __restrict__ pK, float* __restrict__ pV)
{
    const int z   = blockIdx.z;
    const int b   = z & 3;
    const int sel = z >> 2;
    const float* w    = (sel == 0) ? wq : (sel == 1) ? wk : wv;
    const float* bias = (sel == 0) ? bq : (sel == 1) ? bk : bv;
    float*       dst  = (sel == 0) ? pQ : (sel == 1) ? pK : pV;

    const int o0 = blockIdx.y * 128;
    const int t0 = blockIdx.x * 128;
    __shared__ __half As[2][128 * 24];   // [buf][o][k], 6144 B per buf
    __shared__ __half Xs[2][16 * 136];   // [buf][k][t], 4352 B per buf
    const int tid  = threadIdx.x;
    const int warp = tid >> 5, lane = tid & 31;
    const int m0 = (warp >> 1) * 32;
    const int n0 = (warp & 1) * 64;
    const int lq = lane >> 2, lr = lane & 3;
    const float* xb = x + (size_t)b * CC * TT;

    const int ar0 = (tid * 4) >> 4,        ak0 = (tid * 4) & 15;
    const int ar1 = (tid * 4 + 1024) >> 4, ak1 = (tid * 4 + 1024) & 15;
    const int xk0 = (tid * 4) >> 7,        xt0 = (tid * 4) & 127;
    const int xk1 = (tid * 4 + 1024) >> 7, xt1 = (tid * 4 + 1024) & 127;

    float acc[2][8][4] = {};
    float4 av[2], xv[2];

    av[0] = *(const float4*)(w + (size_t)(o0 + ar0) * CC + ak0);
    av[1] = *(const float4*)(w + (size_t)(o0 + ar1) * CC + ak1);
    xv[0] = *(const float4*)(xb + (size_t)xk0 * TT + t0 + xt0);
    xv[1] = *(const float4*)(xb + (size_t)xk1 * TT + t0 + xt1);
    {
        __half* d0 = &As[0][ar0 * 24 + ak0];
        *(__half2*)d0       = __floats2half2_rn(av[0].x, av[0].y);
        *((__half2*)d0 + 1) = __floats2half2_rn(av[0].z, av[0].w);
        __half* d1 = &As[0][ar1 * 24 + ak1];
        *(__half2*)d1       = __floats2half2_rn(av[1].x, av[1].y);
        *((__half2*)d1 + 1) = __floats2half2_rn(av[1].z, av[1].w);
        __half* e0 = &Xs[0][xk0 * 136 + xt0];
        *(__half2*)e0       = __floats2half2_rn(xv[0].x, xv[0].y);
        *((__half2*)e0 + 1) = __floats2half2_rn(xv[0].z, xv[0].w);
        __half* e1 = &Xs[0][xk1 * 136 + xt1];
        *(__half2*)e1       = __floats2half2_rn(xv[1].x, xv[1].y);
        *((__half2*)e1 + 1) = __floats2half2_rn(xv[1].z, xv[1].w);
    }
    __syncthreads();

    const unsigned AsB = (unsigned)__cvta_generic_to_shared(&As[0][0]);
    const unsigned XsB = (unsigned)__cvta_generic_to_shared(&Xs[0][0]);
    const int mm = lane >> 3, r8 = lane & 7;
    const unsigned a_part = ((lane & 15) * 24 + (lane >> 4) * 8) * 2;
    const unsigned b_part = ((((mm & 1) * 8 + r8) * 136) + (mm >> 1) * 8) * 2;

    for (int k0 = 0; k0 < CC; k0 += 16) {
        const int cur = (k0 >> 4) & 1;
        const bool more = (k0 + 16) < CC;
        if (more) {
            const int kn = k0 + 16;
            av[0] = *(const float4*)(w + (size_t)(o0 + ar0) * CC + kn + ak0);
            av[1] = *(const float4*)(w + (size_t)(o0 + ar1) * CC + kn + ak1);
            xv[0] = *(const float4*)(xb + (size_t)(kn + xk0) * TT + t0 + xt0);
            xv[1] = *(const float4*)(xb + (size_t)(kn + xk1) * TT + t0 + xt1);
        }
        unsigned a0[4], a1[4];
        ldmx4(a0[0], a0[1], a0[2], a0[3], AsB + cur * 6144 + m0 * 48 + a_part);
        ldmx4(a1[0], a1[1], a1[2], a1[3], AsB + cur * 6144 + (m0 + 16) * 48 + a_part);
        #pragma unroll
        for (int nt = 0; nt < 4; nt++) {
            unsigned h0, h1, h2, h3;
            ldmx4t(h0, h1, h2, h3, XsB + cur * 4352 + (n0 + nt * 16) * 2 + b_part);
            mma_f16(acc[0][2*nt],   a0[0], a0[1], a0[2], a0[3], h0, h1);
            mma_f16(acc[0][2*nt+1], a0[0], a0[1], a0[2], a0[3], h2, h3);
            mma_f16(acc[1][2*nt],   a1[0], a1[1], a1[2], a1[3], h0, h1);
            mma_f16(acc[1][2*nt+1], a1[0], a1[1], a1[2], a1[3], h2, h3);
        }
        if (more) {
            const int nxt = cur ^ 1;
            __half* d0 = &As[nxt][ar0 * 24 + ak0];
            *(__half2*)d0       = __floats2half2_rn(av[0].x, av[0].y);
            *((__half2*)d0 + 1) = __floats2half2_rn(av[0].z, av[0].w);
            __half* d1 = &As[nxt][ar1 * 24 + ak1];
            *(__half2*)d1       = __floats2half2_rn(av[1].x, av[1].y);
            *((__half2*)d1 + 1) = __floats2half2_rn(av[1].z, av[1].w);
            __half* e0 = &Xs[nxt][xk0 * 136 + xt0];
            *(__half2*)e0       = __floats2half2_rn(xv[0].x, xv[0].y);
            *((__half2*)e0 + 1) = __floats2half2_rn(xv[0].z, xv[0].w);
            __half* e1 = &Xs[nxt][xk1 * 136 + xt1];
            *(__half2*)e1       = __floats2half2_rn(xv[1].x, xv[1].y);
            *((__half2*)e1 + 1) = __floats2half2_rn(xv[1].z, xv[1].w);
        }
        __syncthreads();
    }

    #pragma unroll
    for (int mi = 0; mi < 2; mi++) {
        #pragma unroll
        for (int half = 0; half < 2; half++) {
            int o = o0 + m0 + mi * 16 + half * 8 + lq;
            float bvv = bias[o];
            int h = o >> 6, kc = o & 63;
            float* drow = dst + ((size_t)(b * HH + h) * TT) * KCC + kc;
            #pragma unroll
            for (int nj = 0; nj < 8; nj++) {
                int t = t0 + n0 + nj * 8 + 2 * lr;
                drow[(size_t)t * KCC]       = acc[mi][nj][half * 2 + 0] + bvv;
                drow[(size_t)(t + 1) * KCC] = acc[mi][nj][half * 2 + 1] + bvv;
            }
        }
    }
}

// ---------------------------------------------------------------------------
// MMA banded flash attention, fp16 splits; P single-fp16 in PV (2-term).
// grid (T/128, BH), 256 thr. smem 83456 B -> 2 CTA/SM.
// ---------------------------------------------------------------------------
#define ATTN_SMEM 83456

__global__ __launch_bounds__(256, 2)
void attn_mma_kernel(const float* __restrict__ Q, const float* __restrict__ K,
                     const float* __restrict__ V, const float* __restrict__ embk,
                     const float* __restrict__ embv, float* __restrict__ Out)
{
    extern __shared__ char smem[];
    uint4* Qpk     = (uint4*)(smem);
    __half* Khi    = (__half*)(smem + 32768);
    __half* Klo    = (__half*)(smem + 41984);
    __half* Vhi    = (__half*)(smem + 51200);
    __half* Vlo    = (__half*)(smem + 60416);
    float* pe      = (float*)(smem + 69632);
    float* qe      = (float*)(smem + 74240);
    float* ek      = (float*)(smem + 78848);
    float* ev      = (float*)(smem + 81152);
    float* Qs      = (float*)(smem + 32768);

    const int bh = blockIdx.y;
    const int t0 = blockIdx.x * 128;
    const int tid = threadIdx.x;
    const int w = tid >> 5, lane = tid & 31;
    const int lq = lane >> 2, lr = lane & 3;
    const int R0 = w * 16 + lq;

    for (int lin = tid; lin < 576; lin += 256) { ek[lin] = embk[lin]; ev[lin] = embv[lin]; }
    const float* Qg = Q + ((size_t)bh * TT + t0) * KCC;
    #pragma unroll
    for (int i = 0; i < 8; i++) {
        int lin = tid * 4 + i * 1024;
        int r = lin >> 6, c = lin & 63;
        *(float4*)(Qs + r * 68 + c) = *(const float4*)(Qg + r * 64 + c);
    }
    for (int lin = tid; lin < 1152; lin += 256) pe[lin] = 0.f;
    __syncthreads();

    for (int idx = tid; idx < 1152; idx += 256) {
        int r = idx / 9, d = idx - r * 9;
        float s = 0.f;
        #pragma unroll 8
        for (int c = 0; c < 64; c++) s += Qs[r * 68 + c] * ek[d * 64 + c];
        qe[idx] = s;
    }
    #pragma unroll
    for (int i = 0; i < 8; i++) {
        int ii = tid + i * 256;
        int r = ii >> 4, ks = (ii >> 2) & 3, l2 = ii & 3;
        int c0 = 16 * ks + 2 * l2;
        float x0 = Qs[r * 68 + c0],     x1 = Qs[r * 68 + c0 + 1];
        float x2 = Qs[r * 68 + c0 + 8], x3 = Qs[r * 68 + c0 + 9];
        unsigned h01, l01, h89, l89;
        split2(x0, x1, h01, l01);
        split2(x2, x3, h89, l89);
        Qpk[(r * 4 + ks) * 4 + l2] = make_uint4(h01, h89, l01, l89);
    }
    __syncthreads();

    const int mm = lane >> 3, r8 = lane & 7;
    const unsigned KhiB = (unsigned)__cvta_generic_to_shared(Khi);
    const unsigned KloB = (unsigned)__cvta_generic_to_shared(Klo);
    const unsigned VhiB = (unsigned)__cvta_generic_to_shared(Vhi);
    const unsigned VloB = (unsigned)__cvta_generic_to_shared(Vlo);
    const unsigned k_part = ((((mm >> 1) * 8 + r8) * 72) + (mm & 1) * 8) * 2;
    const unsigned v_part = ((((mm & 1) * 8 + r8) * 72) + (mm >> 1) * 8) * 2;

    int si[4], ci[4];
    #pragma unroll
    for (int i = 0; i < 4; i++) {
        int lin = tid * 4 + i * 1024;
        si[i] = lin >> 6; ci[i] = lin & 63;
    }

    float S[8][4];
    float O[8][4] = {};
    float mr[2] = {-1e30f, -1e30f};
    float lr2[2] = {0.f, 0.f};
    const int jlo = (t0 - 4) < 0 ? 0 : (t0 - 4) >> 6;
    const int jhi = ((t0 + 131) >> 6) > 15 ? 15 : (t0 + 131) >> 6;

    const float* Kbh = K + (size_t)bh * TT * KCC;
    const float* Vbh = V + (size_t)bh * TT * KCC;

    float4 kreg[4];
    #pragma unroll
    for (int i = 0; i < 4; i++) kreg[i] = *(const float4*)(Kbh + si[i] * 64 + ci[i]);

    for (int j = 0; j < 16; j++) {
        const int s0 = j * 64;

        #pragma unroll
        for (int i = 0; i < 4; i++) {
            unsigned h01, l01, h23, l23;
            split2(kreg[i].x, kreg[i].y, h01, l01);
            split2(kreg[i].z, kreg[i].w, h23, l23);
            *(uint2*)(Khi + si[i] * 72 + ci[i]) = make_uint2(h01, h23);
            *(uint2*)(Klo + si[i] * 72 + ci[i]) = make_uint2(l01, l23);
        }
        float4 vreg[4];
        #pragma unroll
        for (int i = 0; i < 4; i++)
            vreg[i] = *(const float4*)(Vbh + (size_t)(s0 + si[i]) * 64 + ci[i]);
        __syncthreads();

        // ---- S = Q K^T (3-term fp16 split) ----
        #pragma unroll
        for (int nt = 0; nt < 8; nt++)
            #pragma unroll
            for (int sl = 0; sl < 4; sl++) S[nt][sl] = 0.f;

        #pragma unroll
        for (int ks = 0; ks < 4; ks++) {
            uint4 qa = Qpk[((R0)     * 4 + ks) * 4 + lr];
            uint4 qb = Qpk[((R0 + 8) * 4 + ks) * 4 + lr];
            #pragma unroll
            for (int ntp = 0; ntp < 4; ntp++) {
                unsigned base = ntp * 2304 + ks * 32 + k_part;
                unsigned h0, h1, h2, h3, g0, g1, g2, g3;
                ldmx4(h0, h1, h2, h3, KhiB + base);
                ldmx4(g0, g1, g2, g3, KloB + base);
                mma_f16(S[2*ntp],   qa.x, qb.x, qa.y, qb.y, h0, h1);
                mma_f16(S[2*ntp+1], qa.x, qb.x, qa.y, qb.y, h2, h3);
                mma_f16(S[2*ntp],   qa.z, qb.z, qa.w, qb.w, h0, h1);
                mma_f16(S[2*ntp+1], qa.z, qb.z, qa.w, qb.w, h2, h3);
                mma_f16(S[2*ntp],   qa.x, qb.x, qa.y, qb.y, g0, g1);
                mma_f16(S[2*ntp+1], qa.x, qb.x, qa.y, qb.y, g2, g3);
            }
        }

        const bool band = (j >= jlo) && (j <= jhi);
        if (band) {
            #pragma unroll
            for (int nt = 0; nt < 8; nt++)
                #pragma unroll
                for (int sl = 0; sl < 4; sl++) {
                    int rl = R0 + ((sl >> 1) << 3);
                    int d = (s0 + nt * 8 + 2 * lr + (sl & 1)) - (t0 + rl) + 4;
                    if (d >= 0 && d <= 8) S[nt][sl] += qe[rl * 9 + d];
                }
        }
        #pragma unroll
        for (int nt = 0; nt < 8; nt++)
            #pragma unroll
            for (int sl = 0; sl < 4; sl++) S[nt][sl] *= 0.125f;

        // ---- online softmax ----
        float alpha[2];
        #pragma unroll
        for (int h = 0; h < 2; h++) {
            float mx = -1e30f;
            #pragma unroll
            for (int nt = 0; nt < 8; nt++)
                mx = fmaxf(mx, fmaxf(S[nt][2*h], S[nt][2*h+1]));
            mx = fmaxf(mx, __shfl_xor_sync(0xffffffffu, mx, 1));
            mx = fmaxf(mx, __shfl_xor_sync(0xffffffffu, mx, 2));
            float mn = fmaxf(mr[h], mx);
            alpha[h] = __expf(mr[h] - mn);
            float rs = 0.f;
            #pragma unroll
            for (int nt = 0; nt < 8; nt++) {
                float p0 = __expf(S[nt][2*h]   - mn);
                float p1 = __expf(S[nt][2*h+1] - mn);
                S[nt][2*h] = p0; S[nt][2*h+1] = p1;
                rs += p0 + p1;
            }
            rs += __shfl_xor_sync(0xffffffffu, rs, 1);
            rs += __shfl_xor_sync(0xffffffffu, rs, 2);
            lr2[h] = lr2[h] * alpha[h] + rs;
            mr[h] = mn;
            #pragma unroll
            for (int nt = 0; nt < 8; nt++) { O[nt][2*h] *= alpha[h]; O[nt][2*h+1] *= alpha[h]; }
        }

        #pragma unroll
        for (int i = 0; i < 4; i++) {
            unsigned h01, l01, h23, l23;
            split2(vreg[i].x, vreg[i].y, h01, l01);
            split2(vreg[i].z, vreg[i].w, h23, l23);
            *(uint2*)(Vhi + si[i] * 72 + ci[i]) = make_uint2(h01, h23);
            *(uint2*)(Vlo + si[i] * 72 + ci[i]) = make_uint2(l01, l23);
        }

        if (lr == 0) {
            #pragma unroll
            for (int h = 0; h < 2; h++)
                if (alpha[h] != 1.0f) {
                    #pragma unroll
                    for (int d = 0; d < 9; d++) pe[(R0 + 8*h) * 9 + d] *= alpha[h];
                }
        }
        __syncwarp();
        if (band) {
            #pragma unroll
            for (int nt = 0; nt < 8; nt++)
                #pragma unroll
                for (int sl = 0; sl < 4; sl++) {
                    int rl = R0 + ((sl >> 1) << 3);
                    int d = (s0 + nt * 8 + 2 * lr + (sl & 1)) - (t0 + rl) + 4;
                    if (d >= 0 && d <= 8) pe[rl * 9 + d] += S[nt][sl];
                }
        }
        __syncthreads();

        if (j < 15) {
            #pragma unroll
            for (int i = 0; i < 4; i++)
                kreg[i] = *(const float4*)(Kbh + (size_t)(s0 + 64 + si[i]) * 64 + ci[i]);
        }

        // ---- O += P V (P single fp16; V hi/lo split: 2 terms) ----
        #pragma unroll
        for (int kp = 0; kp < 4; kp++) {
            unsigned p0 = h2pack(S[2*kp][0],   S[2*kp][1]);
            unsigned p1 = h2pack(S[2*kp][2],   S[2*kp][3]);
            unsigned p2 = h2pack(S[2*kp+1][0], S[2*kp+1][1]);
            unsigned p3 = h2pack(S[2*kp+1][2], S[2*kp+1][3]);
            #pragma unroll
            for (int ntp = 0; ntp < 4; ntp++) {
                unsigned base = kp * 2304 + ntp * 32 + v_part;
                unsigned h0, h1, h2, h3, g0, g1, g2, g3;
                ldmx4t(h0, h1, h2, h3, VhiB + base);
                ldmx4t(g0, g1, g2, g3, VloB + base);
                mma_f16(O[2*ntp],   p0, p1, p2, p3, h0, h1);
                mma_f16(O[2*ntp+1], p0, p1, p2, p3, h2, h3);
                mma_f16(O[2*ntp],   p0, p1, p2, p3, g0, g1);
                mma_f16(O[2*ntp+1], p0, p1, p2, p3, g2, g3);
            }
        }
        __syncthreads();
    }

    float pev0[9], pev1[9];
    #pragma unroll
    for (int d = 0; d < 9; d++) { pev0[d] = pe[R0 * 9 + d]; pev1[d] = pe[(R0 + 8) * 9 + d]; }
    const float il0 = 1.f / lr2[0], il1 = 1.f / lr2[1];
    float* Og = Out + ((size_t)bh * TT + t0) * KCC;
    #pragma unroll
    for (int nt = 0; nt < 8; nt++) {
        int c = nt * 8 + 2 * lr;
        float e0 = 0.f, e1 = 0.f, f0 = 0.f, f1 = 0.f;
        #pragma unroll
        for (int d = 0; d < 9; d++) {
            float v0 = ev[d * 64 + c], v1 = ev[d * 64 + c + 1];
            e0 += pev0[d] * v0; e1 += pev0[d] * v1;
            f0 += pev1[d] * v0; f1 += pev1[d] * v1;
        }
        *(float2*)(Og + (size_t)R0 * 64 + c)       = make_float2((O[nt][0] + e0) * il0,
                                                                 (O[nt][1] + e1) * il0);
        *(float2*)(Og + (size_t)(R0 + 8) * 64 + c) = make_float2((O[nt][2] + f0) * il1,
                                                                 (O[nt][3] + f1) * il1);
    }
}

// ---------------------------------------------------------------------------
// Output projection, fp16 HMMA + ldmatrix, double-buffered, BK=16.
// As[o][k] pitch 24; Xs[t][k] pitch 24 (B via non-trans ldmatrix).
// ---------------------------------------------------------------------------
__global__ __launch_bounds__(256, 2)
void oproj_kernel(const float* __restrict__ w, const float* __restrict__ bias,
                  const float* __restrict__ A, float* __restrict__ out)
{
    const int b  = blockIdx.z;
    const int o0 = blockIdx.y * 128;
    const int t0 = blockIdx.x * 128;
    __shared__ __half As[2][128 * 24];
    __shared__ __half Xs[2][128 * 24];
    const int tid  = threadIdx.x;
    const int warp = tid >> 5, lane = tid & 31;
    const int m0 = (warp >> 1) * 32;
    const int n0 = (warp & 1) * 64;
    const int lq = lane >> 2, lr = lane & 3;

    const int ar0 = (tid * 4) >> 4,        ak0 = (tid * 4) & 15;
    const int ar1 = (tid * 4 + 1024) >> 4, ak1 = (tid * 4 + 1024) & 15;
    const int xt0 = (tid * 4) >> 4,        xk0 = (tid * 4) & 15;
    const int xt1 = (tid * 4 + 1024) >> 4, xk1 = (tid * 4 + 1024) & 15;

    float acc[2][8][4] = {};
    float4 av[2], xv[2];

    av[0] = *(const float4*)(w + (size_t)(o0 + ar0) * CC + ak0);
    av[1] = *(const float4*)(w + (size_t)(o0 + ar1) * CC + ak1);
    xv[0] = *(const float4*)(A + ((size_t)(b * HH + 0) * TT + t0 + xt0) * KCC + xk0);
    xv[1] = *(const float4*)(A + ((size_t)(b * HH + 0) * TT + t0 + xt1) * KCC + xk1);
    {
        __half* d0 = &As[0][ar0 * 24 + ak0];
        *(__half2*)d0       = __floats2half2_rn(av[0].x, av[0].y);
        *((__half2*)d0 + 1) = __floats2half2_rn(av[0].z, av[0].w);
        __half* d1 = &As[0][ar1 * 24 + ak1];
        *(__half2*)d1       = __floats2half2_rn(av[1].x, av[1].y);
        *((__half2*)d1 + 1) = __floats2half2_rn(av[1].z, av[1].w);
        __half* e0 = &Xs[0][xt0 * 24 + xk0];
        *(__half2*)e0       = __floats2half2_rn(xv[0].x, xv[0].y);
        *((__half2*)e0 + 1) = __floats2half2_rn(xv[0].z, xv[0].w);
        __half* e1 = &Xs[0][xt1 * 24 + xk1];
        *(__half2*)e1       = __floats2half2_rn(xv[1].x, xv[1].y);
        *((__half2*)e1 + 1) = __floats2half2_rn(xv[1].z, xv[1].w);
    }
    __syncthreads();

    const unsigned AsB = (unsigned)__cvta_generic_to_shared(&As[0][0]);
    const unsigned XsB = (unsigned)__cvta_generic_to_shared(&Xs[0][0]);
    const unsigned a_part = ((lane & 15) * 24 + (lane >> 4) * 8) * 2;

    for (int k0 = 0; k0 < CC; k0 += 16) {
        const int cur = (k0 >> 4) & 1;
        const bool more = (k0 + 16) < CC;
        if (more) {
            const int kn = k0 + 16;
            const int h = kn >> 6, kc0 = kn & 63;
            av[0] = *(const float4*)(w + (size_t)(o0 + ar0) * CC + kn + ak0);
            av[1] = *(const float4*)(w + (size_t)(o0 + ar1) * CC + kn + ak1);
            xv[0] = *(const float4*)(A + ((size_t)(b * HH + h) * TT + t0 + xt0) * KCC + kc0 + xk0);
            xv[1] = *(const float4*)(A + ((size_t)(b * HH + h) * TT + t0 + xt1) * KCC + kc0 + xk1);
        }
        unsigned a0[4], a1[4];
        ldmx4(a0[0], a0[1], a0[2], a0[3], AsB + cur * 6144 + m0 * 48 + a_part);
        ldmx4(a1[0], a1[1], a1[2], a1[3], AsB + cur * 6144 + (m0 + 16) * 48 + a_part);
        #pragma unroll
        for (int nt = 0; nt < 4; nt++) {
            unsigned h0, h1, h2, h3;
            ldmx4(h0, h1, h2, h3, XsB + cur * 6144 + (n0 + nt * 16) * 48 + a_part);
            mma_f16(acc[0][2*nt],   a0[0], a0[1], a0[2], a0[3], h0, h2);
            mma_f16(acc[0][2*nt+1], a0[0], a0[1], a0[2], a0[3], h1, h3);
            mma_f16(acc[1][2*nt],   a1[0], a1[1], a1[2], a1[3], h0, h2);
            mma_f16(acc[1][2*nt+1], a1[0], a1[1], a1[2], a1[3], h1, h3);
        }
        if (more) {
            const int nxt = cur ^ 1;
            __half* d0 = &As[nxt][ar0 * 24 + ak0];
            *(__half2*)d0       = __floats2half2_rn(av[0].x, av[0].y);
            *((__half2*)d0 + 1) = __floats2half2_rn(av[0].z, av[0].w);
            __half* d1 = &As[nxt][ar1 * 24 + ak1];
            *(__half2*)d1       = __floats2half2_rn(av[1].x, av[1].y);
            *((__half2*)d1 + 1) = __floats2half2_rn(av[1].z, av[1].w);
            __half* e0 = &Xs[nxt][xt0 * 24 + xk0];
            *(__half2*)e0       = __floats2half2_rn(xv[0].x, xv[0].y);
            *((__half2*)e0 + 1) = __floats2half2_rn(xv[0].z, xv[0].w);
            __half* e1 = &Xs[nxt][xt1 * 24 + xk1];
            *(__half2*)e1       = __floats2half2_rn(xv[1].x, xv[1].y);
            *((__half2*)e1 + 1) = __floats2half2_rn(xv[1].z, xv[1].w);
        }
        __syncthreads();
    }

    #pragma unroll
    for (int mi = 0; mi < 2; mi++) {
        #pragma unroll
        for (int half = 0; half < 2; half++) {
            int o = o0 + m0 + mi * 16 + half * 8 + lq;
            float bvv = bias[o];
            float* orow = out + ((size_t)b * CC + o) * TT;
            #pragma unroll
            for (int nj = 0; nj < 8; nj++) {
                int t = t0 + n0 + nj * 8 + 2 * lr;
                *(float2*)(orow + t) = make_float2(acc[mi][nj][half * 2 + 0] + bvv,
                                                   acc[mi][nj][half * 2 + 1] + bvv);
            }
        }
    }
}

// ---------------------------------------------------------------------------
extern "C" void kernel_launch(void* const* d_in, const int* in_sizes, int n_in,
                              void* d_out, int out_size)
{
    const float* x   = (const float*)d_in[0];
    const float* wq  = (const float*)d_in[1];
    const float* bq  = (const float*)d_in[2];
    const float* wk  = (const float*)d_in[3];
    const float* bk  = (const float*)d_in[4];
    const float* wv  = (const float*)d_in[5];
    const float* bv  = (const float*)d_in[6];
    const float* wo  = (const float*)d_in[7];
    const float* bo  = (const float*)d_in[8];
    const float* ek  = (const float*)d_in[9];
    const float* ev  = (const float*)d_in[10];
    float* out = (float*)d_out;

    float *pQ, *pK, *pV, *pO;
    cudaGetSymbolAddress((void**)&pQ, g_Q);
    cudaGetSymbolAddress((void**)&pK, g_K);
    cudaGetSymbolAddress((void**)&pV, g_V);
    cudaGetSymbolAddress((void**)&pO, g_O);

    static int configured = 0;
    if (!configured) {
        cudaFuncSetAttribute((const void*)attn_mma_kernel,
                             cudaFuncAttributeMaxDynamicSharedMemorySize, ATTN_SMEM);
        configured = 1;
    }

    proj3_kernel<<<dim3(TT / 128, CC / 128, BB * 3), 256>>>(wq, bq, wk, bk, wv, bv, x, pQ, pK, pV);
    attn_mma_kernel<<<dim3(TT / 128, BHT), 256, ATTN_SMEM>>>(pQ, pK, pV, ek, ev, pO);
    oproj_kernel<<<dim3(TT / 128, CC / 128, BB), 256>>>(wo, bo, pO, out);
}